// round 1
// baseline (speedup 1.0000x reference)
#include <cuda_runtime.h>
#include <cstdint>

// Embedding gather: out[token, :] = weight[input[token], :]
// input: [32768] int32 (d_in[0]), weight: [50257*512] f32 (d_in[1])
// out:   [32768*512] f32
//
// Vectorized as float4: each row = 512 f32 = 128 float4.
// Thread gid handles token = gid>>7, column-chunk = gid&127.
// 128 consecutive threads read the same index (uniform broadcast) and do a
// fully coalesced 2048B row copy (LDG.E.128 -> STG.E.128).

__global__ __launch_bounds__(256) void embed_gather_kernel(
    const int* __restrict__ idx,
    const float4* __restrict__ weight4,
    float4* __restrict__ out4,
    int total_vec)   // = n_tokens * 128
{
    int gid = blockIdx.x * blockDim.x + threadIdx.x;
    if (gid >= total_vec) return;
    int token = gid >> 7;        // / 128
    int col   = gid & 127;       // % 128
    int row   = __ldg(idx + token);
    out4[gid] = __ldg(weight4 + (long long)row * 128 + col);
}

extern "C" void kernel_launch(void* const* d_in, const int* in_sizes, int n_in,
                              void* d_out, int out_size) {
    const int*   idx     = (const int*)d_in[0];     // [8*4096] int32
    const float* weight  = (const float*)d_in[1];   // [50257*512] f32
    float*       out     = (float*)d_out;           // [8*4096*512] f32

    int n_tokens  = in_sizes[0];          // 32768
    int total_vec = n_tokens * 128;       // float4 chunks

    int threads = 256;
    int blocks  = (total_vec + threads - 1) / threads;
    embed_gather_kernel<<<blocks, threads>>>(
        idx, (const float4*)weight, (float4*)out, total_vec);
}

// round 2
// speedup vs baseline: 1.6061x; 1.6061x over previous
#include <cuda_runtime.h>
#include <cstdint>

// Embedding gather: out[token, :] = weight[input[token], :]
// input: [32768] int32 (d_in[0]), weight: [50257, 512] f32 (d_in[1])
// out:   [32768, 512] f32
//
// One WARP per token row. Row = 512 f32 = 128 float4.
// Thread t handles float4 columns {t, t+32, t+64, t+96}: 4 independent
// 128B-coalesced warp loads in flight (MLP=4) to hide the ~577cyc DRAM
// latency. Index is loaded once per warp. Output stores use streaming
// hint (.cs) so the 67MB write stream doesn't evict weight rows from L2.

__global__ __launch_bounds__(256) void embed_gather_warp_row(
    const int* __restrict__ idx,
    const float4* __restrict__ weight4,
    float4* __restrict__ out4,
    int n_tokens)
{
    const int warp_id = (blockIdx.x * blockDim.x + threadIdx.x) >> 5;
    const int lane    = threadIdx.x & 31;
    if (warp_id >= n_tokens) return;

    const int row = __ldg(idx + warp_id);

    const float4* __restrict__ src = weight4 + (long long)row * 128 + lane;
    float4* __restrict__ dst       = out4    + (long long)warp_id * 128 + lane;

    // 4 independent loads issued before any store (front-batched MLP=4)
    float4 v0 = __ldg(src);
    float4 v1 = __ldg(src + 32);
    float4 v2 = __ldg(src + 64);
    float4 v3 = __ldg(src + 96);

    __stcs(dst,      v0);
    __stcs(dst + 32, v1);
    __stcs(dst + 64, v2);
    __stcs(dst + 96, v3);
}

extern "C" void kernel_launch(void* const* d_in, const int* in_sizes, int n_in,
                              void* d_out, int out_size) {
    const int*   idx    = (const int*)d_in[0];     // [8*4096] int32
    const float* weight = (const float*)d_in[1];   // [50257*512] f32
    float*       out    = (float*)d_out;

    int n_tokens = in_sizes[0];                    // 32768
    int threads  = 256;                            // 8 warps -> 8 tokens/block
    int blocks   = (n_tokens * 32 + threads - 1) / threads;  // 4096
    embed_gather_warp_row<<<blocks, threads>>>(
        idx, (const float4*)weight, (float4*)out, n_tokens);
}